// round 1
// baseline (speedup 1.0000x reference)
#include <cuda_runtime.h>
#include <cuda_bf16.h>
#include <math.h>

// Problem constants
#define B_  2
#define N_  2048
#define DM_ 128
#define H_  8
#define DK_ 16
#define R_  4
#define GRID_ 64
#define NCELL (GRID_*GRID_)   // 4096
#define NP1 (N_+1)            // 2049

// ---------------- scratch (device globals; no allocs allowed) ----------------
__device__ float g_Q[B_*N_*DM_];        // [B][N][128]
__device__ float g_K[B_*NP1*DM_];       // [B][N+1][128]
__device__ float g_V[B_*NP1*DM_];
__device__ float g_att[B_*N_*DM_];      // attention output (pre out-proj)
__device__ int   g_counts[B_*NCELL];
__device__ int   g_offsets[B_*NCELL];
__device__ int   g_cursor[B_*NCELL];
__device__ int   g_items[B_*N_];

// ---------------- binning ----------------
__global__ void zero_kernel() {
    int i = blockIdx.x * blockDim.x + threadIdx.x;   // 32*512 = 16384
    if (i < B_*NCELL) g_counts[i] = 0;
    else              g_cursor[i - B_*NCELL] = 0;
}

__global__ void count_kernel(const int* __restrict__ pos, const float* __restrict__ alive) {
    int qid = blockIdx.x * blockDim.x + threadIdx.x;  // 0..4095
    if (qid >= B_*N_) return;
    if (alive[qid] == 0.f) return;
    int b = qid >> 11;
    int x = pos[qid*2+0], y = pos[qid*2+1];
    atomicAdd(&g_counts[b*NCELL + x*GRID_ + y], 1);
}

// exclusive prefix sum of 4096 counts per batch; grid=B, block=128
__global__ void scan_kernel() {
    int b = blockIdx.x;
    int tid = threadIdx.x;
    int base = b*NCELL + tid*32;
    int local[32];
    int s = 0;
#pragma unroll
    for (int k = 0; k < 32; k++) { local[k] = s; s += g_counts[base+k]; }
    __shared__ int sh[128];
    sh[tid] = s;
    __syncthreads();
    for (int off = 1; off < 128; off <<= 1) {
        int v = (tid >= off) ? sh[tid-off] : 0;
        __syncthreads();
        sh[tid] += v;
        __syncthreads();
    }
    int prefix = (tid == 0) ? 0 : sh[tid-1];
#pragma unroll
    for (int k = 0; k < 32; k++) g_offsets[base+k] = prefix + local[k];
}

__global__ void scatter_kernel(const int* __restrict__ pos, const float* __restrict__ alive) {
    int qid = blockIdx.x * blockDim.x + threadIdx.x;
    if (qid >= B_*N_) return;
    if (alive[qid] == 0.f) return;
    int b = qid >> 11, n = qid & (N_-1);
    int x = pos[qid*2+0], y = pos[qid*2+1];
    int cell = b*NCELL + x*GRID_ + y;
    int slot = atomicAdd(&g_cursor[cell], 1);
    g_items[b*N_ + g_offsets[cell] + slot] = n;
}

// ---------------- QKV projection GEMM ----------------
// grid = (64, 3). which: 0=Q, 1=K, 2=V. Rows = z[b][n]*alive[b][n].
__global__ __launch_bounds__(256) void qkv_gemm(
    const float* __restrict__ z, const float* __restrict__ alive,
    const float* __restrict__ Wq, const float* __restrict__ bq,
    const float* __restrict__ Wk, const float* __restrict__ bk,
    const float* __restrict__ Wv, const float* __restrict__ bv)
{
    int which = blockIdx.y;
    const float* W    = (which == 0) ? Wq : (which == 1) ? Wk : Wv;
    const float* bias = (which == 0) ? bq : (which == 1) ? bk : bv;

    __shared__ float As[64][17];
    __shared__ float Ws[16][128];

    int tid = threadIdx.x;
    int row0 = blockIdx.x * 64;
    int tr = tid >> 5;            // 0..7
    int tc = (tid & 31) * 4;      // col 0..124

    float acc[8][4];
#pragma unroll
    for (int r = 0; r < 8; r++)
#pragma unroll
        for (int c = 0; c < 4; c++) acc[r][c] = bias[tc+c];

    for (int kt = 0; kt < 8; kt++) {
        // load A tile 64x16 with alive scaling
        for (int i = tid; i < 64*16; i += 256) {
            int r = i >> 4, kk = i & 15;
            int grow = row0 + r;
            As[r][kk] = z[grow*DM_ + kt*16 + kk] * alive[grow];
        }
        // load W tile 16x128
        for (int i = tid; i < 16*128; i += 256) {
            int kk = i >> 7, c = i & 127;
            Ws[kk][c] = W[(kt*16 + kk)*DM_ + c];
        }
        __syncthreads();
#pragma unroll
        for (int kk = 0; kk < 16; kk++) {
            float4 wv = *reinterpret_cast<const float4*>(&Ws[kk][tc]);
#pragma unroll
            for (int r = 0; r < 8; r++) {
                float a = As[tr*8 + r][kk];
                acc[r][0] = fmaf(a, wv.x, acc[r][0]);
                acc[r][1] = fmaf(a, wv.y, acc[r][1]);
                acc[r][2] = fmaf(a, wv.z, acc[r][2]);
                acc[r][3] = fmaf(a, wv.w, acc[r][3]);
            }
        }
        __syncthreads();
    }
#pragma unroll
    for (int r = 0; r < 8; r++) {
        int grow = row0 + tr*8 + r;
        int b = grow >> 11, n = grow & (N_-1);
        float4 val = make_float4(acc[r][0], acc[r][1], acc[r][2], acc[r][3]);
        if (which == 0) {
            *reinterpret_cast<float4*>(&g_Q[grow*DM_ + tc]) = val;
        } else {
            float* dst = (which == 1) ? g_K : g_V;
            *reinterpret_cast<float4*>(&dst[(b*NP1 + n)*DM_ + tc]) = val;
        }
    }
}

// patch token K/V rows; grid = B, block = 256
__global__ void patch_proj(const float* __restrict__ pt,
                           const float* __restrict__ Wk, const float* __restrict__ bk,
                           const float* __restrict__ Wv, const float* __restrict__ bv)
{
    int b = blockIdx.x;
    int tid = threadIdx.x;
    __shared__ float p[128];
    if (tid < 128) p[tid] = pt[b*DM_ + tid];
    __syncthreads();
    int c = tid & 127;
    const float* W    = (tid < 128) ? Wk : Wv;
    const float* bias = (tid < 128) ? bk : bv;
    float acc = bias[c];
#pragma unroll 8
    for (int k = 0; k < 128; k++) acc = fmaf(p[k], W[k*DM_ + c], acc);
    float* dst = (tid < 128) ? g_K : g_V;
    dst[(b*NP1 + N_)*DM_ + c] = acc;
}

// ---------------- sparse attention, warp per query ----------------
__global__ __launch_bounds__(256) void attn_kernel(
    const int* __restrict__ pos, const float* __restrict__ alive,
    const float* __restrict__ rel_bias)
{
    __shared__ float sbias[H_*81];
    int tid = threadIdx.x;
    for (int i = tid; i < H_*81; i += 256) sbias[i] = rel_bias[i];
    __syncthreads();

    int warp = tid >> 5, lane = tid & 31;
    int qid = blockIdx.x * 8 + warp;           // 0..4095
    int b = qid >> 11, n = qid & (N_-1);
    int h = lane >> 2, s = lane & 3;
    int hoff = h * DK_;
    float* outp = g_att + qid*DM_;

    if (alive[qid] == 0.f) {
        reinterpret_cast<float4*>(outp)[lane] = make_float4(0.f, 0.f, 0.f, 0.f);
        return;
    }

    // load q fragment for this head
    float q[16];
    {
        const float4* qp = reinterpret_cast<const float4*>(g_Q + qid*DM_ + hoff);
#pragma unroll
        for (int u = 0; u < 4; u++) {
            float4 f = qp[u];
            q[4*u+0] = f.x; q[4*u+1] = f.y; q[4*u+2] = f.z; q[4*u+3] = f.w;
        }
    }
    int xi = pos[qid*2+0], yi = pos[qid*2+1];

    const float* kbase = g_K + b*NP1*DM_;
    const float* vbase = g_V + b*NP1*DM_;

    float m, l, acc[16];
    // patch token: counted once (slot 0 only)
    {
        const float* kp = kbase + N_*DM_ + hoff;
        float d = 0.f;
#pragma unroll
        for (int u = 0; u < 16; u++) d = fmaf(q[u], kp[u], d);
        float lg = 0.25f * d;
        if (s == 0) {
            m = lg; l = 1.f;
            const float* vp = vbase + N_*DM_ + hoff;
#pragma unroll
            for (int u = 0; u < 16; u++) acc[u] = vp[u];
        } else {
            m = -1e30f; l = 0.f;
#pragma unroll
            for (int u = 0; u < 16; u++) acc[u] = 0.f;
        }
    }

    auto process = [&](int j, float rel) {
        const float* kj = kbase + j*DM_ + hoff;
        float d = 0.f;
        const float4* k4 = reinterpret_cast<const float4*>(kj);
#pragma unroll
        for (int u = 0; u < 4; u++) {
            float4 f = k4[u];
            d = fmaf(q[4*u+0], f.x, d);
            d = fmaf(q[4*u+1], f.y, d);
            d = fmaf(q[4*u+2], f.z, d);
            d = fmaf(q[4*u+3], f.w, d);
        }
        float lg = fmaf(d, 0.25f, rel);
        float nm = fmaxf(m, lg);
        float fac = __expf(m - nm);
        float p   = __expf(lg - nm);
        m = nm;
        l = l * fac + p;
        const float4* v4 = reinterpret_cast<const float4*>(vbase + j*DM_ + hoff);
#pragma unroll
        for (int u = 0; u < 4; u++) {
            float4 f = v4[u];
            acc[4*u+0] = acc[4*u+0]*fac + p*f.x;
            acc[4*u+1] = acc[4*u+1]*fac + p*f.y;
            acc[4*u+2] = acc[4*u+2]*fac + p*f.z;
            acc[4*u+3] = acc[4*u+3]*fac + p*f.w;
        }
    };

    // iterate 9x9 cell window; distribute neighbor stream over 4 slots
    int t = 0;
    int myj = -1;
    float myrel = 0.f;
    int x0 = max(xi - R_, 0), x1 = min(xi + R_, GRID_-1);
    int y0 = max(yi - R_, 0), y1 = min(yi + R_, GRID_-1);
    for (int cx = x0; cx <= x1; cx++) {
        for (int cy = y0; cy <= y1; cy++) {
            int cell = b*NCELL + cx*GRID_ + cy;
            int st  = g_offsets[cell];
            int cnt = g_counts[cell];
            float rb = sbias[h*81 + (cx - xi + R_)*9 + (cy - yi + R_)];
            for (int e = 0; e < cnt; e++) {
                int j = g_items[b*N_ + st + e];
                if (j == n) continue;            // self-exclusion (warp-uniform)
                if ((t & 3) == s) { myj = j; myrel = rb; }
                t++;
                if ((t & 3) == 0) {              // warp-uniform condition
                    process(myj, myrel);
                    myj = -1;
                }
            }
        }
    }
    if (myj >= 0) process(myj, myrel);           // tail (some lanes idle)

    // reduce across the 4 slots of each head (lanes h*4 .. h*4+3)
    unsigned full = 0xffffffffu;
    float gm = m;
    gm = fmaxf(gm, __shfl_xor_sync(full, gm, 1));
    gm = fmaxf(gm, __shfl_xor_sync(full, gm, 2));
    float fac = __expf(m - gm);
    l *= fac;
    l += __shfl_xor_sync(full, l, 1);
    l += __shfl_xor_sync(full, l, 2);
#pragma unroll
    for (int u = 0; u < 16; u++) {
        acc[u] *= fac;
        acc[u] += __shfl_xor_sync(full, acc[u], 1);
        acc[u] += __shfl_xor_sync(full, acc[u], 2);
    }
    if (s == 0) {
        float inv = 1.f / l;
        float4* o4 = reinterpret_cast<float4*>(outp + hoff);
#pragma unroll
        for (int u = 0; u < 4; u++)
            o4[u] = make_float4(acc[4*u+0]*inv, acc[4*u+1]*inv,
                                acc[4*u+2]*inv, acc[4*u+3]*inv);
    }
}

// ---------------- output projection ----------------
__global__ __launch_bounds__(256) void out_gemm(
    const float* __restrict__ alive,
    const float* __restrict__ Wo, const float* __restrict__ bo,
    float* __restrict__ out)
{
    __shared__ float As[64][17];
    __shared__ float Ws[16][128];
    int tid = threadIdx.x;
    int row0 = blockIdx.x * 64;
    int tr = tid >> 5;
    int tc = (tid & 31) * 4;

    float acc[8][4];
#pragma unroll
    for (int r = 0; r < 8; r++)
#pragma unroll
        for (int c = 0; c < 4; c++) acc[r][c] = bo[tc+c];

    for (int kt = 0; kt < 8; kt++) {
        for (int i = tid; i < 64*16; i += 256) {
            int r = i >> 4, kk = i & 15;
            As[r][kk] = g_att[(row0 + r)*DM_ + kt*16 + kk];
        }
        for (int i = tid; i < 16*128; i += 256) {
            int kk = i >> 7, c = i & 127;
            Ws[kk][c] = Wo[(kt*16 + kk)*DM_ + c];
        }
        __syncthreads();
#pragma unroll
        for (int kk = 0; kk < 16; kk++) {
            float4 wv = *reinterpret_cast<const float4*>(&Ws[kk][tc]);
#pragma unroll
            for (int r = 0; r < 8; r++) {
                float a = As[tr*8 + r][kk];
                acc[r][0] = fmaf(a, wv.x, acc[r][0]);
                acc[r][1] = fmaf(a, wv.y, acc[r][1]);
                acc[r][2] = fmaf(a, wv.z, acc[r][2]);
                acc[r][3] = fmaf(a, wv.w, acc[r][3]);
            }
        }
        __syncthreads();
    }
#pragma unroll
    for (int r = 0; r < 8; r++) {
        int grow = row0 + tr*8 + r;
        float av = alive[grow];
        float4 val = make_float4(acc[r][0]*av, acc[r][1]*av, acc[r][2]*av, acc[r][3]*av);
        *reinterpret_cast<float4*>(&out[grow*DM_ + tc]) = val;
    }
}

// ---------------- launch ----------------
extern "C" void kernel_launch(void* const* d_in, const int* in_sizes, int n_in,
                              void* d_out, int out_size)
{
    const float* z     = (const float*)d_in[0];
    const float* pt    = (const float*)d_in[1];
    const int*   pos   = (const int*)  d_in[2];
    const float* alive = (const float*)d_in[3];
    const float* Wq    = (const float*)d_in[4];
    const float* bq    = (const float*)d_in[5];
    const float* Wk    = (const float*)d_in[6];
    const float* bk    = (const float*)d_in[7];
    const float* Wv    = (const float*)d_in[8];
    const float* bv    = (const float*)d_in[9];
    const float* Wo    = (const float*)d_in[10];
    const float* bo    = (const float*)d_in[11];
    const float* rel   = (const float*)d_in[12];
    float* out = (float*)d_out;

    zero_kernel<<<32, 512>>>();
    count_kernel<<<16, 256>>>(pos, alive);
    scan_kernel<<<B_, 128>>>();
    scatter_kernel<<<16, 256>>>(pos, alive);
    qkv_gemm<<<dim3(64, 3), 256>>>(z, alive, Wq, bq, Wk, bk, Wv, bv);
    patch_proj<<<B_, 256>>>(pt, Wk, bk, Wv, bv);
    attn_kernel<<<512, 256>>>(pos, alive, rel);
    out_gemm<<<64, 256>>>(alive, Wo, bo, out);
}

// round 2
// speedup vs baseline: 1.1769x; 1.1769x over previous
#include <cuda_runtime.h>
#include <cuda_bf16.h>
#include <math.h>

#define B_  2
#define N_  2048
#define DM_ 128
#define H_  8
#define DK_ 16
#define R_  4
#define GRID_ 64
#define NCELL (GRID_*GRID_)   // 4096
#define NP1 (N_+1)            // 2049

typedef unsigned long long ull;

// ---------------- scratch (device globals; no allocs allowed) ----------------
__device__ float g_Q[B_*N_*DM_];
__device__ float g_K[B_*NP1*DM_];
__device__ float g_V[B_*NP1*DM_];
__device__ float g_att[B_*N_*DM_];
__device__ int   g_cellinfo[B_*NCELL];   // (start<<16) | count
__device__ int   g_items[B_*N_];

// ---------------- f32x2 helpers ----------------
__device__ __forceinline__ ull pk2(float lo, float hi) {
    ull r; asm("mov.b64 %0, {%1,%2};" : "=l"(r) : "f"(lo), "f"(hi)); return r;
}
__device__ __forceinline__ void upk2(ull v, float& lo, float& hi) {
    asm("mov.b64 {%0,%1}, %2;" : "=f"(lo), "=f"(hi) : "l"(v));
}
__device__ __forceinline__ void fma2(ull& d, ull a, ull b) {
    asm("fma.rn.f32x2 %0, %1, %2, %0;" : "+l"(d) : "l"(a), "l"(b));
}

// ============================================================================
// Fused kernel #1: QKV projection GEMM + patch-token K/V rows + spatial binning
// grid = (66, 3), block = 256
//   blockIdx.x in [0,64): GEMM tile (64 rows) for which = blockIdx.y (0=Q,1=K,2=V)
//   blockIdx.x == 64:     patch rows (which 1,2 only)
//   blockIdx.x == 65:     binning for batch = which (0,1 only)
// ============================================================================
__global__ __launch_bounds__(256) void fused_qkv(
    const float* __restrict__ z, const float* __restrict__ alive,
    const int*   __restrict__ pos, const float* __restrict__ pt,
    const float* __restrict__ Wq, const float* __restrict__ bq,
    const float* __restrict__ Wk, const float* __restrict__ bk,
    const float* __restrict__ Wv, const float* __restrict__ bv)
{
    __shared__ __align__(16) unsigned char smem_raw[16896];
    int tid = threadIdx.x;
    int which = blockIdx.y;
    int bx = blockIdx.x;

    if (bx == 65) {
        // ---- binning for batch b = which ----
        if (which >= B_) return;
        int b = which;
        int* cnt  = reinterpret_cast<int*>(smem_raw);           // 4096 ints
        int* wsum = reinterpret_cast<int*>(smem_raw + 16384);   // 8 ints
        for (int i = tid; i < NCELL; i += 256) cnt[i] = 0;
        __syncthreads();
        int mycell[8];
#pragma unroll
        for (int u = 0; u < 8; u++) {
            int n = tid + u*256;
            int qid = b*N_ + n;
            mycell[u] = -1;
            if (alive[qid] != 0.f) {
                int2 p = reinterpret_cast<const int2*>(pos)[qid];
                mycell[u] = p.x*GRID_ + p.y;
                atomicAdd(&cnt[mycell[u]], 1);
            }
        }
        __syncthreads();
        // scan: each thread owns 16 consecutive cells
        int base = tid*16;
        int c[16], s = 0;
#pragma unroll
        for (int k2 = 0; k2 < 16; k2++) { c[k2] = cnt[base+k2]; s += c[k2]; }
        int lane = tid & 31, wid = tid >> 5;
        int v = s;
#pragma unroll
        for (int off = 1; off < 32; off <<= 1) {
            int t = __shfl_up_sync(0xffffffffu, v, off);
            if (lane >= off) v += t;
        }
        if (lane == 31) wsum[wid] = v;
        __syncthreads();
        if (tid < 8) {
            int w = wsum[tid];
#pragma unroll
            for (int off = 1; off < 8; off <<= 1) {
                int t = __shfl_up_sync(0xffu, w, off);
                if (tid >= off) w += t;
            }
            wsum[tid] = w;
        }
        __syncthreads();
        int run = v - s + (wid > 0 ? wsum[wid-1] : 0);
        int starts[16];
#pragma unroll
        for (int k2 = 0; k2 < 16; k2++) {
            starts[k2] = run;
            g_cellinfo[b*NCELL + base + k2] = (run << 16) | c[k2];
            run += c[k2];
        }
        __syncthreads();
#pragma unroll
        for (int k2 = 0; k2 < 16; k2++) cnt[base+k2] = starts[k2];
        __syncthreads();
#pragma unroll
        for (int u = 0; u < 8; u++) {
            if (mycell[u] >= 0) {
                int slot = atomicAdd(&cnt[mycell[u]], 1);
                g_items[b*N_ + slot] = tid + u*256;
            }
        }
        return;
    }

    if (bx == 64) {
        // ---- patch-token K/V rows ----
        if (which == 0) return;
        float* p = reinterpret_cast<float*>(smem_raw);  // 2 x 128
        {
            int bb = tid >> 7, cc = tid & 127;
            p[tid] = pt[bb*DM_ + cc];
        }
        __syncthreads();
        int bb = tid >> 7, cc = tid & 127;
        const float* W    = (which == 1) ? Wk : Wv;
        const float* bias = (which == 1) ? bk : bv;
        const float* pr = p + bb*128;
        float acc = bias[cc];
#pragma unroll 8
        for (int k2 = 0; k2 < 128; k2++) acc = fmaf(pr[k2], W[k2*DM_ + cc], acc);
        float* dst = (which == 1) ? g_K : g_V;
        dst[(bb*NP1 + N_)*DM_ + cc] = acc;
        return;
    }

    // ---- GEMM tile: 64 rows x 128 cols, K=128, f32x2 packed ----
    const float* W    = (which == 0) ? Wq : (which == 1) ? Wk : Wv;
    const float* bias = (which == 0) ? bq : (which == 1) ? bk : bv;

    ull (*As2)[17] = reinterpret_cast<ull(*)[17]>(smem_raw);           // 64x17 ull = 8704B
    ull (*Ws2)[64] = reinterpret_cast<ull(*)[64]>(smem_raw + 8704);    // 16x64 ull = 8192B

    int row0 = bx * 64;
    int tr = tid >> 5;            // 0..7
    int lane = tid & 31;
    int tc = lane * 4;            // col 0..124
    int pairc = lane * 2;

    ull accA[8], accB[8];
    {
        ull b01 = pk2(bias[tc], bias[tc+1]);
        ull b23 = pk2(bias[tc+2], bias[tc+3]);
#pragma unroll
        for (int r = 0; r < 8; r++) { accA[r] = b01; accB[r] = b23; }
    }

    for (int kt = 0; kt < 8; kt++) {
        for (int i = tid; i < 64*16; i += 256) {
            int r = i >> 4, kk = i & 15;
            int grow = row0 + r;
            float a = z[grow*DM_ + kt*16 + kk] * alive[grow];
            As2[r][kk] = pk2(a, a);
        }
        for (int i = tid; i < 16*32; i += 256) {
            int kk = i >> 5, c4 = i & 31;
            float4 w = *reinterpret_cast<const float4*>(&W[(kt*16 + kk)*DM_ + c4*4]);
            Ws2[kk][c4*2]   = pk2(w.x, w.y);
            Ws2[kk][c4*2+1] = pk2(w.z, w.w);
        }
        __syncthreads();
#pragma unroll
        for (int kk = 0; kk < 16; kk++) {
            ulonglong2 wp = *reinterpret_cast<const ulonglong2*>(&Ws2[kk][pairc]);
#pragma unroll
            for (int r = 0; r < 8; r++) {
                ull aa = As2[tr*8 + r][kk];
                fma2(accA[r], aa, wp.x);
                fma2(accB[r], aa, wp.y);
            }
        }
        __syncthreads();
    }
#pragma unroll
    for (int r = 0; r < 8; r++) {
        int grow = row0 + tr*8 + r;
        int b = grow >> 11, n = grow & (N_-1);
        float4 val;
        upk2(accA[r], val.x, val.y);
        upk2(accB[r], val.z, val.w);
        if (which == 0) {
            *reinterpret_cast<float4*>(&g_Q[grow*DM_ + tc]) = val;
        } else {
            float* dst = (which == 1) ? g_K : g_V;
            *reinterpret_cast<float4*>(&dst[(b*NP1 + n)*DM_ + tc]) = val;
        }
    }
}

// ============================================================================
// Sparse attention, warp per query
// ============================================================================
__global__ __launch_bounds__(256) void attn_kernel(
    const int* __restrict__ pos, const float* __restrict__ alive,
    const float* __restrict__ rel_bias)
{
    __shared__ float sbias[H_*81];
    int tid = threadIdx.x;
    for (int i = tid; i < H_*81; i += 256) sbias[i] = rel_bias[i];
    __syncthreads();

    int warp = tid >> 5, lane = tid & 31;
    int qid = blockIdx.x * 8 + warp;
    int b = qid >> 11, n = qid & (N_-1);
    int h = lane >> 2, s = lane & 3;
    int hoff = h * DK_;
    float* outp = g_att + qid*DM_;

    if (alive[qid] == 0.f) {
        reinterpret_cast<float4*>(outp)[lane] = make_float4(0.f, 0.f, 0.f, 0.f);
        return;
    }

    float q[16];
    {
        const float4* qp = reinterpret_cast<const float4*>(g_Q + qid*DM_ + hoff);
#pragma unroll
        for (int u = 0; u < 4; u++) {
            float4 f = qp[u];
            q[4*u+0] = f.x; q[4*u+1] = f.y; q[4*u+2] = f.z; q[4*u+3] = f.w;
        }
    }
    int xi = pos[qid*2+0], yi = pos[qid*2+1];

    const float* kbase = g_K + b*NP1*DM_;
    const float* vbase = g_V + b*NP1*DM_;

    float m, l, acc[16];
    {
        const float* kp = kbase + N_*DM_ + hoff;
        float d = 0.f;
#pragma unroll
        for (int u = 0; u < 16; u++) d = fmaf(q[u], kp[u], d);
        float lg = 0.25f * d;
        if (s == 0) {
            m = lg; l = 1.f;
            const float* vp = vbase + N_*DM_ + hoff;
#pragma unroll
            for (int u = 0; u < 16; u++) acc[u] = vp[u];
        } else {
            m = -1e30f; l = 0.f;
#pragma unroll
            for (int u = 0; u < 16; u++) acc[u] = 0.f;
        }
    }

    auto process = [&](int j, float rel) {
        const float4* k4 = reinterpret_cast<const float4*>(kbase + j*DM_ + hoff);
        float d = 0.f;
#pragma unroll
        for (int u = 0; u < 4; u++) {
            float4 f = k4[u];
            d = fmaf(q[4*u+0], f.x, d);
            d = fmaf(q[4*u+1], f.y, d);
            d = fmaf(q[4*u+2], f.z, d);
            d = fmaf(q[4*u+3], f.w, d);
        }
        float lg = fmaf(d, 0.25f, rel);
        float nm = fmaxf(m, lg);
        float fac = __expf(m - nm);
        float p   = __expf(lg - nm);
        m = nm;
        l = l * fac + p;
        const float4* v4 = reinterpret_cast<const float4*>(vbase + j*DM_ + hoff);
#pragma unroll
        for (int u = 0; u < 4; u++) {
            float4 f = v4[u];
            acc[4*u+0] = acc[4*u+0]*fac + p*f.x;
            acc[4*u+1] = acc[4*u+1]*fac + p*f.y;
            acc[4*u+2] = acc[4*u+2]*fac + p*f.z;
            acc[4*u+3] = acc[4*u+3]*fac + p*f.w;
        }
    };

    int t = 0;
    int myj = -1;
    float myrel = 0.f;
    int x0 = max(xi - R_, 0), x1 = min(xi + R_, GRID_-1);
    int y0 = max(yi - R_, 0), y1 = min(yi + R_, GRID_-1);
    for (int cx = x0; cx <= x1; cx++) {
        for (int cy = y0; cy <= y1; cy++) {
            int info = g_cellinfo[b*NCELL + cx*GRID_ + cy];
            int cnt = info & 0xffff;
            int st  = info >> 16;
            float rb = sbias[h*81 + (cx - xi + R_)*9 + (cy - yi + R_)];
            for (int e = 0; e < cnt; e++) {
                int j = g_items[b*N_ + st + e];
                if (j == n) continue;
                if ((t & 3) == s) { myj = j; myrel = rb; }
                t++;
                if ((t & 3) == 0) {
                    process(myj, myrel);
                    myj = -1;
                }
            }
        }
    }
    if (myj >= 0) process(myj, myrel);

    unsigned full = 0xffffffffu;
    float gm = m;
    gm = fmaxf(gm, __shfl_xor_sync(full, gm, 1));
    gm = fmaxf(gm, __shfl_xor_sync(full, gm, 2));
    float fac = __expf(m - gm);
    l *= fac;
    l += __shfl_xor_sync(full, l, 1);
    l += __shfl_xor_sync(full, l, 2);
#pragma unroll
    for (int u = 0; u < 16; u++) {
        acc[u] *= fac;
        acc[u] += __shfl_xor_sync(full, acc[u], 1);
        acc[u] += __shfl_xor_sync(full, acc[u], 2);
    }
    if (s == 0) {
        float inv = 1.f / l;
        float4* o4 = reinterpret_cast<float4*>(outp + hoff);
#pragma unroll
        for (int u = 0; u < 4; u++)
            o4[u] = make_float4(acc[4*u+0]*inv, acc[4*u+1]*inv,
                                acc[4*u+2]*inv, acc[4*u+3]*inv);
    }
}

// ============================================================================
// Output projection GEMM (f32x2 packed), x alive on output
// ============================================================================
__global__ __launch_bounds__(256) void out_gemm(
    const float* __restrict__ alive,
    const float* __restrict__ Wo, const float* __restrict__ bo,
    float* __restrict__ out)
{
    __shared__ __align__(16) unsigned char smem_raw[16896];
    ull (*As2)[17] = reinterpret_cast<ull(*)[17]>(smem_raw);
    ull (*Ws2)[64] = reinterpret_cast<ull(*)[64]>(smem_raw + 8704);

    int tid = threadIdx.x;
    int row0 = blockIdx.x * 64;
    int tr = tid >> 5;
    int lane = tid & 31;
    int tc = lane * 4;
    int pairc = lane * 2;

    ull accA[8], accB[8];
    {
        ull b01 = pk2(bo[tc], bo[tc+1]);
        ull b23 = pk2(bo[tc+2], bo[tc+3]);
#pragma unroll
        for (int r = 0; r < 8; r++) { accA[r] = b01; accB[r] = b23; }
    }

    for (int kt = 0; kt < 8; kt++) {
        for (int i = tid; i < 64*16; i += 256) {
            int r = i >> 4, kk = i & 15;
            float a = g_att[(row0 + r)*DM_ + kt*16 + kk];
            As2[r][kk] = pk2(a, a);
        }
        for (int i = tid; i < 16*32; i += 256) {
            int kk = i >> 5, c4 = i & 31;
            float4 w = *reinterpret_cast<const float4*>(&Wo[(kt*16 + kk)*DM_ + c4*4]);
            Ws2[kk][c4*2]   = pk2(w.x, w.y);
            Ws2[kk][c4*2+1] = pk2(w.z, w.w);
        }
        __syncthreads();
#pragma unroll
        for (int kk = 0; kk < 16; kk++) {
            ulonglong2 wp = *reinterpret_cast<const ulonglong2*>(&Ws2[kk][pairc]);
#pragma unroll
            for (int r = 0; r < 8; r++) {
                ull aa = As2[tr*8 + r][kk];
                fma2(accA[r], aa, wp.x);
                fma2(accB[r], aa, wp.y);
            }
        }
        __syncthreads();
    }
#pragma unroll
    for (int r = 0; r < 8; r++) {
        int grow = row0 + tr*8 + r;
        float av = alive[grow];
        float4 val;
        upk2(accA[r], val.x, val.y);
        upk2(accB[r], val.z, val.w);
        val.x *= av; val.y *= av; val.z *= av; val.w *= av;
        *reinterpret_cast<float4*>(&out[grow*DM_ + tc]) = val;
    }
}

// ---------------- launch ----------------
extern "C" void kernel_launch(void* const* d_in, const int* in_sizes, int n_in,
                              void* d_out, int out_size)
{
    const float* z     = (const float*)d_in[0];
    const float* pt    = (const float*)d_in[1];
    const int*   pos   = (const int*)  d_in[2];
    const float* alive = (const float*)d_in[3];
    const float* Wq    = (const float*)d_in[4];
    const float* bq    = (const float*)d_in[5];
    const float* Wk    = (const float*)d_in[6];
    const float* bk    = (const float*)d_in[7];
    const float* Wv    = (const float*)d_in[8];
    const float* bv    = (const float*)d_in[9];
    const float* Wo    = (const float*)d_in[10];
    const float* bo    = (const float*)d_in[11];
    const float* rel   = (const float*)d_in[12];
    float* out = (float*)d_out;

    fused_qkv<<<dim3(66, 3), 256>>>(z, alive, pos, pt, Wq, bq, Wk, bk, Wv, bv);
    attn_kernel<<<512, 256>>>(pos, alive, rel);
    out_gemm<<<64, 256>>>(alive, Wo, bo, out);
}

// round 3
// speedup vs baseline: 1.5486x; 1.3159x over previous
#include <cuda_runtime.h>
#include <cuda_bf16.h>
#include <math.h>

#define B_  2
#define N_  2048
#define DM_ 128
#define H_  8
#define DK_ 16
#define R_  4
#define GRID_ 64
#define NCELL (GRID_*GRID_)   // 4096
#define NP1 (N_+1)            // 2049

typedef unsigned long long ull;

// ---------------- scratch ----------------
__device__ float g_Q[B_*N_*DM_];
__device__ float g_K[B_*NP1*DM_];
__device__ float g_V[B_*NP1*DM_];
__device__ float g_att[B_*N_*DM_];
__device__ int   g_cellinfo[B_*NCELL];   // (start<<16) | count
__device__ int   g_items[B_*N_];

// ---------------- f32x2 helpers ----------------
__device__ __forceinline__ ull pk2(float lo, float hi) {
    ull r; asm("mov.b64 %0, {%1,%2};" : "=l"(r) : "f"(lo), "f"(hi)); return r;
}
__device__ __forceinline__ void upk2(ull v, float& lo, float& hi) {
    asm("mov.b64 {%0,%1}, %2;" : "=f"(lo), "=f"(hi) : "l"(v));
}
__device__ __forceinline__ void fma2(ull& d, ull a, ull b) {
    asm("fma.rn.f32x2 %0, %1, %2, %0;" : "+l"(d) : "l"(a), "l"(b));
}

// ============================================================================
// Fused kernel #1: merged QKV GEMM + patch rows + binning.  grid = 132
//   bx in [0,128): GEMM tile of 32 rows x 128 cols, all 3 matrices
//   bx == 128: patch-token K rows,  bx == 129: patch-token V rows
//   bx == 130: binning batch 0,     bx == 131: binning batch 1
// ============================================================================
__global__ __launch_bounds__(256) void fused_qkv(
    const float* __restrict__ z, const float* __restrict__ alive,
    const int*   __restrict__ pos, const float* __restrict__ pt,
    const float* __restrict__ Wq, const float* __restrict__ bq,
    const float* __restrict__ Wk, const float* __restrict__ bk,
    const float* __restrict__ Wv, const float* __restrict__ bv)
{
    __shared__ __align__(16) unsigned char smem_raw[29440];
    int tid = threadIdx.x;
    int bx = blockIdx.x;

    if (bx >= 130) {
        // ---- binning for batch b ----
        int b = bx - 130;
        int* cnt  = reinterpret_cast<int*>(smem_raw);           // 4096 ints
        int* wsum = reinterpret_cast<int*>(smem_raw + 16384);   // 8 ints
        for (int i = tid; i < NCELL; i += 256) cnt[i] = 0;
        __syncthreads();
        int mycell[8];
#pragma unroll
        for (int u = 0; u < 8; u++) {
            int n = tid + u*256;
            int qid = b*N_ + n;
            mycell[u] = -1;
            if (alive[qid] != 0.f) {
                int2 p = reinterpret_cast<const int2*>(pos)[qid];
                mycell[u] = p.x*GRID_ + p.y;
                atomicAdd(&cnt[mycell[u]], 1);
            }
        }
        __syncthreads();
        int base = tid*16;
        int c[16], s = 0;
#pragma unroll
        for (int k2 = 0; k2 < 16; k2++) { c[k2] = cnt[base+k2]; s += c[k2]; }
        int lane = tid & 31, wid = tid >> 5;
        int v = s;
#pragma unroll
        for (int off = 1; off < 32; off <<= 1) {
            int t = __shfl_up_sync(0xffffffffu, v, off);
            if (lane >= off) v += t;
        }
        if (lane == 31) wsum[wid] = v;
        __syncthreads();
        if (tid < 8) {
            int w = wsum[tid];
#pragma unroll
            for (int off = 1; off < 8; off <<= 1) {
                int t = __shfl_up_sync(0xffu, w, off);
                if (tid >= off) w += t;
            }
            wsum[tid] = w;
        }
        __syncthreads();
        int run = v - s + (wid > 0 ? wsum[wid-1] : 0);
        int starts[16];
#pragma unroll
        for (int k2 = 0; k2 < 16; k2++) {
            starts[k2] = run;
            g_cellinfo[b*NCELL + base + k2] = (run << 16) | c[k2];
            run += c[k2];
        }
        __syncthreads();
#pragma unroll
        for (int k2 = 0; k2 < 16; k2++) cnt[base+k2] = starts[k2];
        __syncthreads();
#pragma unroll
        for (int u = 0; u < 8; u++) {
            if (mycell[u] >= 0) {
                int slot = atomicAdd(&cnt[mycell[u]], 1);
                g_items[b*N_ + slot] = tid + u*256;
            }
        }
        return;
    }

    if (bx >= 128) {
        // ---- patch-token rows: bx==128 -> K, bx==129 -> V ----
        int isV = bx - 128;
        float* p = reinterpret_cast<float*>(smem_raw);  // 256 floats
        p[tid] = pt[tid];
        __syncthreads();
        int bb = tid >> 7, cc = tid & 127;
        const float* W    = isV ? Wv : Wk;
        const float* bias = isV ? bv : bk;
        const float* pr = p + bb*128;
        float acc = bias[cc];
#pragma unroll 8
        for (int k2 = 0; k2 < 128; k2++) acc = fmaf(pr[k2], W[k2*DM_ + cc], acc);
        float* dst = isV ? g_V : g_K;
        dst[(bb*NP1 + N_)*DM_ + cc] = acc;
        return;
    }

    // ---- merged GEMM tile: 32 rows x 128 cols, 3 matrices ----
    ull (*As2)[18]     = reinterpret_cast<ull(*)[18]>(smem_raw);             // 32x18 ull = 4608B
    ull (*Ws2)[16][64] = reinterpret_cast<ull(*)[16][64]>(smem_raw + 4608);  // 3x16x64 ull = 24576B
    float* salive      = reinterpret_cast<float*>(smem_raw + 29184);         // 32 floats

    int row0 = bx * 32;
    int w = tid >> 5;             // warp 0..7 -> rows w*4..w*4+3
    int lane = tid & 31;
    int tc = lane * 4;            // cols
    int pairc = lane * 2;
    int w4 = w * 4;

    if (tid < 32) salive[tid] = alive[row0 + tid];

    ull acc[3][4][2];
    {
        const float* biases[3] = {bq, bk, bv};
#pragma unroll
        for (int mat = 0; mat < 3; mat++) {
            float4 bv4 = *reinterpret_cast<const float4*>(&biases[mat][tc]);
            ull b01 = pk2(bv4.x, bv4.y);
            ull b23 = pk2(bv4.z, bv4.w);
#pragma unroll
            for (int r = 0; r < 4; r++) { acc[mat][r][0] = b01; acc[mat][r][1] = b23; }
        }
    }
    __syncthreads();

    for (int kt = 0; kt < 8; kt++) {
        // A tile: 32 rows x 16 k, packed (a,a); 128 float4 loads
        if (tid < 128) {
            int r = tid >> 2, c4 = tid & 3;
            float av = salive[r];
            float4 a4 = *reinterpret_cast<const float4*>(&z[(row0 + r)*DM_ + kt*16 + c4*4]);
            ulonglong2* dst = reinterpret_cast<ulonglong2*>(&As2[r][c4*4]);
            dst[0] = make_ulonglong2(pk2(a4.x*av, a4.x*av), pk2(a4.y*av, a4.y*av));
            dst[1] = make_ulonglong2(pk2(a4.z*av, a4.z*av), pk2(a4.w*av, a4.w*av));
        }
        // W tiles: 3 x 16 x 128 floats = 1536 float4; 6 per thread
        {
            const float* Ws_[3] = {Wq, Wk, Wv};
#pragma unroll
            for (int it = 0; it < 6; it++) {
                int i = tid + it*256;
                int mat = i >> 9, rem = i & 511;
                int kk = rem >> 5, c4 = rem & 31;
                float4 wv4 = *reinterpret_cast<const float4*>(&Ws_[mat][(kt*16 + kk)*DM_ + c4*4]);
                *reinterpret_cast<ulonglong2*>(&Ws2[mat][kk][c4*2]) =
                    make_ulonglong2(pk2(wv4.x, wv4.y), pk2(wv4.z, wv4.w));
            }
        }
        __syncthreads();
#pragma unroll
        for (int p = 0; p < 8; p++) {
            int kk0 = p*2;
            ulonglong2 aa[4];
#pragma unroll
            for (int r = 0; r < 4; r++)
                aa[r] = *reinterpret_cast<const ulonglong2*>(&As2[w4 + r][kk0]);
#pragma unroll
            for (int mat = 0; mat < 3; mat++) {
                ulonglong2 w0 = *reinterpret_cast<const ulonglong2*>(&Ws2[mat][kk0][pairc]);
                ulonglong2 w1 = *reinterpret_cast<const ulonglong2*>(&Ws2[mat][kk0+1][pairc]);
#pragma unroll
                for (int r = 0; r < 4; r++) {
                    fma2(acc[mat][r][0], aa[r].x, w0.x);
                    fma2(acc[mat][r][1], aa[r].x, w0.y);
                    fma2(acc[mat][r][0], aa[r].y, w1.x);
                    fma2(acc[mat][r][1], aa[r].y, w1.y);
                }
            }
        }
        __syncthreads();
    }
#pragma unroll
    for (int r = 0; r < 4; r++) {
        int grow = row0 + w4 + r;
        int b = grow >> 11, n = grow & (N_-1);
        float4 val;
        upk2(acc[0][r][0], val.x, val.y);
        upk2(acc[0][r][1], val.z, val.w);
        *reinterpret_cast<float4*>(&g_Q[grow*DM_ + tc]) = val;
        upk2(acc[1][r][0], val.x, val.y);
        upk2(acc[1][r][1], val.z, val.w);
        *reinterpret_cast<float4*>(&g_K[(b*NP1 + n)*DM_ + tc]) = val;
        upk2(acc[2][r][0], val.x, val.y);
        upk2(acc[2][r][1], val.z, val.w);
        *reinterpret_cast<float4*>(&g_V[(b*NP1 + n)*DM_ + tc]) = val;
    }
}

// ============================================================================
// Sparse attention, warp per query
// ============================================================================
__global__ __launch_bounds__(256) void attn_kernel(
    const int* __restrict__ pos, const float* __restrict__ alive,
    const float* __restrict__ rel_bias)
{
    __shared__ float sbias[H_*81];
    __shared__ int   sinfo[8][96];
    int tid = threadIdx.x;
    for (int i = tid; i < H_*81; i += 256) sbias[i] = rel_bias[i];
    __syncthreads();

    int warp = tid >> 5, lane = tid & 31;
    int qid = blockIdx.x * 8 + warp;
    int b = qid >> 11, n = qid & (N_-1);
    int h = lane >> 2, s = lane & 3;
    int hoff = h * DK_;
    float* outp = g_att + qid*DM_;

    if (alive[qid] == 0.f) {
        reinterpret_cast<float4*>(outp)[lane] = make_float4(0.f, 0.f, 0.f, 0.f);
        return;
    }

    float q[16];
    {
        const float4* qp = reinterpret_cast<const float4*>(g_Q + qid*DM_ + hoff);
#pragma unroll
        for (int u = 0; u < 4; u++) {
            float4 f = qp[u];
            q[4*u+0] = f.x; q[4*u+1] = f.y; q[4*u+2] = f.z; q[4*u+3] = f.w;
        }
    }
    int2 pxy = reinterpret_cast<const int2*>(pos)[qid];
    int xi = pxy.x, yi = pxy.y;

    const float* kbase = g_K + b*NP1*DM_;
    const float* vbase = g_V + b*NP1*DM_;
    const int* items = g_items + b*N_;

    // lane-parallel prefetch of cell infos into smem:
    // packed (biasidx<<24) | (start<<12) | count
    int x0 = max(xi - R_, 0), x1 = min(xi + R_, GRID_-1);
    int y0 = max(yi - R_, 0), y1 = min(yi + R_, GRID_-1);
    int ny = y1 - y0 + 1;
    int ncells = (x1 - x0 + 1) * ny;
    for (int idx = lane; idx < ncells; idx += 32) {
        int cx = x0 + idx / ny, cy = y0 + idx % ny;
        int info = g_cellinfo[b*NCELL + (cx << 6) + cy];
        int bidx = (cx - xi + R_)*9 + (cy - yi + R_);
        sinfo[warp][idx] = (bidx << 24) | ((info >> 16) << 12) | (info & 0xffff);
    }
    __syncwarp();

    float m, l, acc[16];
    {
        const float* kp = kbase + N_*DM_ + hoff;
        float d = 0.f;
#pragma unroll
        for (int u = 0; u < 16; u++) d = fmaf(q[u], kp[u], d);
        float lg = 0.25f * d;
        if (s == 0) {
            m = lg; l = 1.f;
            const float* vp = vbase + N_*DM_ + hoff;
#pragma unroll
            for (int u = 0; u < 16; u++) acc[u] = vp[u];
        } else {
            m = -1e30f; l = 0.f;
#pragma unroll
            for (int u = 0; u < 16; u++) acc[u] = 0.f;
        }
    }

    auto process = [&](int j, float rel) {
        const float4* k4 = reinterpret_cast<const float4*>(kbase + j*DM_ + hoff);
        float d = 0.f;
#pragma unroll
        for (int u = 0; u < 4; u++) {
            float4 f = k4[u];
            d = fmaf(q[4*u+0], f.x, d);
            d = fmaf(q[4*u+1], f.y, d);
            d = fmaf(q[4*u+2], f.z, d);
            d = fmaf(q[4*u+3], f.w, d);
        }
        float lg = fmaf(d, 0.25f, rel);
        float nm = fmaxf(m, lg);
        float fac = __expf(m - nm);
        float p   = __expf(lg - nm);
        m = nm;
        l = l * fac + p;
        const float4* v4 = reinterpret_cast<const float4*>(vbase + j*DM_ + hoff);
#pragma unroll
        for (int u = 0; u < 4; u++) {
            float4 f = v4[u];
            acc[4*u+0] = acc[4*u+0]*fac + p*f.x;
            acc[4*u+1] = acc[4*u+1]*fac + p*f.y;
            acc[4*u+2] = acc[4*u+2]*fac + p*f.z;
            acc[4*u+3] = acc[4*u+3]*fac + p*f.w;
        }
    };

    int t = 0;
    int myj = -1;
    float myrel = 0.f;
    for (int ci = 0; ci < ncells; ci++) {
        int val = sinfo[warp][ci];
        int cnt = val & 0xfff;
        int st  = (val >> 12) & 0xfff;
        float rb = sbias[h*81 + (val >> 24)];
        for (int e = 0; e < cnt; e++) {
            int j = items[st + e];
            if (j == n) continue;
            if ((t & 3) == s) { myj = j; myrel = rb; }
            t++;
            if ((t & 3) == 0) {
                process(myj, myrel);
                myj = -1;
            }
        }
    }
    if (myj >= 0) process(myj, myrel);

    unsigned full = 0xffffffffu;
    float gm = m;
    gm = fmaxf(gm, __shfl_xor_sync(full, gm, 1));
    gm = fmaxf(gm, __shfl_xor_sync(full, gm, 2));
    float fac = __expf(m - gm);
    l *= fac;
    l += __shfl_xor_sync(full, l, 1);
    l += __shfl_xor_sync(full, l, 2);
#pragma unroll
    for (int u = 0; u < 16; u++) {
        acc[u] *= fac;
        acc[u] += __shfl_xor_sync(full, acc[u], 1);
        acc[u] += __shfl_xor_sync(full, acc[u], 2);
    }
    if (s == 0) {
        float inv = 1.f / l;
        float4* o4 = reinterpret_cast<float4*>(outp + hoff);
#pragma unroll
        for (int u = 0; u < 4; u++)
            o4[u] = make_float4(acc[4*u+0]*inv, acc[4*u+1]*inv,
                                acc[4*u+2]*inv, acc[4*u+3]*inv);
    }
}

// ============================================================================
// Output projection GEMM: 128 blocks x 32 rows, f32x2, x alive
// ============================================================================
__global__ __launch_bounds__(256) void out_gemm(
    const float* __restrict__ alive,
    const float* __restrict__ Wo, const float* __restrict__ bo,
    float* __restrict__ out)
{
    __shared__ __align__(16) unsigned char smem_raw[12800];
    ull (*As2)[18] = reinterpret_cast<ull(*)[18]>(smem_raw);           // 4608B
    ull (*Ws2)[64] = reinterpret_cast<ull(*)[64]>(smem_raw + 4608);    // 16x64 ull = 8192B

    int tid = threadIdx.x;
    int row0 = blockIdx.x * 32;
    int w = tid >> 5;
    int lane = tid & 31;
    int tc = lane * 4;
    int pairc = lane * 2;
    int w4 = w * 4;

    ull acc[4][2];
    {
        float4 bv4 = *reinterpret_cast<const float4*>(&bo[tc]);
        ull b01 = pk2(bv4.x, bv4.y);
        ull b23 = pk2(bv4.z, bv4.w);
#pragma unroll
        for (int r = 0; r < 4; r++) { acc[r][0] = b01; acc[r][1] = b23; }
    }

    for (int kt = 0; kt < 8; kt++) {
        if (tid < 128) {
            int r = tid >> 2, c4 = tid & 3;
            float4 a4 = *reinterpret_cast<const float4*>(&g_att[(row0 + r)*DM_ + kt*16 + c4*4]);
            ulonglong2* dst = reinterpret_cast<ulonglong2*>(&As2[r][c4*4]);
            dst[0] = make_ulonglong2(pk2(a4.x, a4.x), pk2(a4.y, a4.y));
            dst[1] = make_ulonglong2(pk2(a4.z, a4.z), pk2(a4.w, a4.w));
        }
#pragma unroll
        for (int it = 0; it < 2; it++) {
            int i = tid + it*256;
            int kk = i >> 5, c4 = i & 31;
            float4 wv4 = *reinterpret_cast<const float4*>(&Wo[(kt*16 + kk)*DM_ + c4*4]);
            *reinterpret_cast<ulonglong2*>(&Ws2[kk][c4*2]) =
                make_ulonglong2(pk2(wv4.x, wv4.y), pk2(wv4.z, wv4.w));
        }
        __syncthreads();
#pragma unroll
        for (int p = 0; p < 8; p++) {
            int kk0 = p*2;
            ulonglong2 aa[4];
#pragma unroll
            for (int r = 0; r < 4; r++)
                aa[r] = *reinterpret_cast<const ulonglong2*>(&As2[w4 + r][kk0]);
            ulonglong2 w0 = *reinterpret_cast<const ulonglong2*>(&Ws2[kk0][pairc]);
            ulonglong2 w1 = *reinterpret_cast<const ulonglong2*>(&Ws2[kk0+1][pairc]);
#pragma unroll
            for (int r = 0; r < 4; r++) {
                fma2(acc[r][0], aa[r].x, w0.x);
                fma2(acc[r][1], aa[r].x, w0.y);
                fma2(acc[r][0], aa[r].y, w1.x);
                fma2(acc[r][1], aa[r].y, w1.y);
            }
        }
        __syncthreads();
    }
#pragma unroll
    for (int r = 0; r < 4; r++) {
        int grow = row0 + w4 + r;
        float av = alive[grow];
        float4 val;
        upk2(acc[r][0], val.x, val.y);
        upk2(acc[r][1], val.z, val.w);
        val.x *= av; val.y *= av; val.z *= av; val.w *= av;
        *reinterpret_cast<float4*>(&out[grow*DM_ + tc]) = val;
    }
}

// ---------------- launch ----------------
extern "C" void kernel_launch(void* const* d_in, const int* in_sizes, int n_in,
                              void* d_out, int out_size)
{
    const float* z     = (const float*)d_in[0];
    const float* pt    = (const float*)d_in[1];
    const int*   pos   = (const int*)  d_in[2];
    const float* alive = (const float*)d_in[3];
    const float* Wq    = (const float*)d_in[4];
    const float* bq    = (const float*)d_in[5];
    const float* Wk    = (const float*)d_in[6];
    const float* bk    = (const float*)d_in[7];
    const float* Wv    = (const float*)d_in[8];
    const float* bv    = (const float*)d_in[9];
    const float* Wo    = (const float*)d_in[10];
    const float* bo    = (const float*)d_in[11];
    const float* rel   = (const float*)d_in[12];
    float* out = (float*)d_out;

    fused_qkv<<<132, 256>>>(z, alive, pos, pt, Wq, bq, Wk, bk, Wv, bv);
    attn_kernel<<<512, 256>>>(pos, alive, rel);
    out_gemm<<<128, 256>>>(alive, Wo, bo, out);
}